// round 15
// baseline (speedup 1.0000x reference)
#include <cuda_runtime.h>
#include <cuda_bf16.h>
#include <cuda_fp16.h>

#define DMODEL 1024
#define NHEADS 16
#define DK     64
#define BATCH  4
#define SEQ    2048
#define MROWS  (BATCH * SEQ)              // 8192
#define SZ     ((size_t)MROWS * DMODEL)   // 8388608 elems
#define WSZ    ((size_t)DMODEL * DMODEL)

typedef unsigned int u32;
typedef unsigned short u16;
typedef __nv_bfloat16 bf16;

// ---------------------------------------------------------------------------
// Device scratch (no allocation allowed)
// ---------------------------------------------------------------------------
__device__ half g_act[6 * SZ];    // [aq_h, aq_l, ak_h, ak_l, av_h, av_l] split-fp16
__device__ half g_prjh[3 * SZ];   // [q, k, v] single fp16
__device__ half g_o[2 * SZ];      // [o_h, o_l] split-fp16
__device__ half g_wh[4 * WSZ];    // [wqT, wkT, wvT, woT] single fp16 (transposed)

// ---------------------------------------------------------------------------
// PTX helpers (base-ISA only: ldmatrix + mma.sync + cp.async)
// ---------------------------------------------------------------------------
__device__ __forceinline__ u32 cvta_s(const void* p) {
    u32 a; asm("{ .reg .u64 t; cvta.to.shared.u64 t, %1; cvt.u32.u64 %0, t; }"
               : "=r"(a) : "l"(p)); return a;
}
__device__ __forceinline__ void sts128(u32 a, uint4 v) {
    asm volatile("st.shared.v4.b32 [%0], {%1,%2,%3,%4};"
                 :: "r"(a), "r"(v.x), "r"(v.y), "r"(v.z), "r"(v.w) : "memory");
}
__device__ __forceinline__ void cpa16(u32 s, const void* g) {
    asm volatile("{ .reg .u64 gg; cvta.to.global.u64 gg, %1;"
                 "  cp.async.cg.shared.global [%0], [gg], 16; }"
                 :: "r"(s), "l"(g) : "memory");
}
__device__ __forceinline__ void cpcommit() { asm volatile("cp.async.commit_group;" ::: "memory"); }
__device__ __forceinline__ void cpwait1()  { asm volatile("cp.async.wait_group 1;" ::: "memory"); }
__device__ __forceinline__ void cpwait0()  { asm volatile("cp.async.wait_group 0;" ::: "memory"); }

#define SWZ(x) ((x) ^ (((x) >> 3) & 0x70))

__device__ __forceinline__ void ldmx4(u32& r0, u32& r1, u32& r2, u32& r3, u32 a) {
    asm volatile("ldmatrix.sync.aligned.m8n8.x4.shared.b16 {%0,%1,%2,%3}, [%4];"
                 : "=r"(r0), "=r"(r1), "=r"(r2), "=r"(r3) : "r"(a));
}
__device__ __forceinline__ void ldmx4t(u32& r0, u32& r1, u32& r2, u32& r3, u32 a) {
    asm volatile("ldmatrix.sync.aligned.m8n8.x4.trans.shared.b16 {%0,%1,%2,%3}, [%4];"
                 : "=r"(r0), "=r"(r1), "=r"(r2), "=r"(r3) : "r"(a));
}
// fp16 MMA
__device__ __forceinline__ void mma16816h(float* d, const u32* a, const u32* b) {
    asm volatile(
        "mma.sync.aligned.m16n8k16.row.col.f32.f16.f16.f32 "
        "{%0,%1,%2,%3}, {%4,%5,%6,%7}, {%8,%9}, {%0,%1,%2,%3};"
        : "+f"(d[0]), "+f"(d[1]), "+f"(d[2]), "+f"(d[3])
        : "r"(a[0]), "r"(a[1]), "r"(a[2]), "r"(a[3]), "r"(b[0]), "r"(b[1]));
}
// fp16 helpers (x0 -> low half)
__device__ __forceinline__ u32 pack2h(float x0, float x1) {
    __half2 hh = __floats2half2_rn(x0, x1);
    return *reinterpret_cast<u32*>(&hh);
}
__device__ __forceinline__ void split_pack_h(float x0, float x1, u32& hp, u32& lp) {
    __half2 hh = __floats2half2_rn(x0, x1);
    hp = *reinterpret_cast<u32*>(&hh);
    float r0 = x0 - __low2float(hh);
    float r1 = x1 - __high2float(hh);
    __half2 ll = __floats2half2_rn(r0, r1);
    lp = *reinterpret_cast<u32*>(&ll);
}

// ---------------------------------------------------------------------------
// Pointer-bundle structs (passed by value to fused kernels)
// ---------------------------------------------------------------------------
struct ConvActArgs { const float* x[3]; half* h[3]; half* l[3]; };
struct ConvWArgs   { const float* W[4]; half* T[4]; };
struct QKVArgs {
    const half* Ah[3]; const half* Al[3]; const half* Bh[3];
    const float* bias[3]; half* Out[3];
};

// ---------------------------------------------------------------------------
// Fused conversion kernels
// ---------------------------------------------------------------------------
// fp32 -> split-fp16 (hi + lo); grid.z selects tensor
__global__ __launch_bounds__(256) void conv_act(ConvActArgs args, int n4)
{
    int i = blockIdx.x * 256 + threadIdx.x;
    if (i >= n4) return;
    const float* x = args.x[blockIdx.z];
    half* h = args.h[blockIdx.z];
    half* l = args.l[blockIdx.z];
    float4 v = ((const float4*)x)[i];
    float vv[4] = {v.x, v.y, v.z, v.w};
    u32 hp[2], lp[2];
#pragma unroll
    for (int e = 0; e < 2; ++e)
        split_pack_h(vv[2 * e], vv[2 * e + 1], hp[e], lp[e]);
    ((uint2*)h)[i] = make_uint2(hp[0], hp[1]);
    ((uint2*)l)[i] = make_uint2(lp[0], lp[1]);
}

// W[k][n] fp32 -> Wt[n][k] single fp16 (transpose through smem); grid.z selects
__global__ __launch_bounds__(256) void conv_w(ConvWArgs args)
{
    __shared__ float ts[32][33];
    const float* W = args.W[blockIdx.z];
    half* T = args.T[blockIdx.z];
    int tx = threadIdx.x, ty = threadIdx.y;         // 32 x 8
    int x0 = blockIdx.x * 32, y0 = blockIdx.y * 32; // x: n, y: k
#pragma unroll
    for (int i = 0; i < 4; ++i)
        ts[ty + i * 8][tx] = W[(size_t)(y0 + ty + i * 8) * DMODEL + x0 + tx];
    __syncthreads();
#pragma unroll
    for (int i = 0; i < 4; ++i) {
        int n = x0 + ty + i * 8, k = y0 + tx;
        T[(size_t)n * DMODEL + k] = __float2half_rn(ts[tx][ty + i * 8]);
    }
}

// ---------------------------------------------------------------------------
// 2-product split-A fp16 GEMM mainloop (shared by QKV and final kernels)
// Block 128x128, K-chunk 64, 8 warps (64x32 warp tile).
// smem: 2 stages x [Ah 16K][Al 16K][B 16K] = 96 KB.
// Occupancy 1 — forcing 2 CTAs/SM caps regs at 128 and spills the 64-float
// accumulator (round-12 regression: 1040 -> 1228 us).
// ---------------------------------------------------------------------------
#define G2_ISSUE(st, k0) do {                                                \
    u32 bs_ = sb + (u32)(st) * 49152u;                                       \
    _Pragma("unroll")                                                        \
    for (int it_ = 0; it_ < 4; ++it_) {                                      \
        int i_ = tid + it_ * 256;                                            \
        int row_ = i_ >> 3, c_ = i_ & 7;                                     \
        u32 so_ = SWZ((u32)(row_ * 128 + c_ * 16));                          \
        size_t ao_ = (size_t)(m0 + row_) * DMODEL + (k0) + c_ * 8;           \
        size_t bo_ = (size_t)(n0 + row_) * DMODEL + (k0) + c_ * 8;           \
        cpa16(bs_ + so_,          Ah + ao_);                                 \
        cpa16(bs_ + 16384u + so_, Al + ao_);                                 \
        cpa16(bs_ + 32768u + so_, Bh + bo_);                                 \
    }                                                                        \
    cpcommit();                                                              \
} while (0)

// Computes the 128x128 tile accumulator; caller handles the epilogue.
__device__ __forceinline__ void gemm2_mainloop(
    const half* __restrict__ Ah, const half* __restrict__ Al,
    const half* __restrict__ Bh,
    u32 sb, int tid, int m0, int n0, int wm, int wn, int lane,
    float acc[4][4][4])
{
#pragma unroll
    for (int mi = 0; mi < 4; ++mi)
#pragma unroll
        for (int nt = 0; nt < 4; ++nt)
#pragma unroll
            for (int e = 0; e < 4; ++e) acc[mi][nt][e] = 0.f;

    G2_ISSUE(0, 0);
    for (int kc = 0; kc < 16; ++kc) {
        if (kc < 15) G2_ISSUE((kc + 1) & 1, (kc + 1) * 64);
        if (kc < 15) cpwait1(); else cpwait0();
        __syncthreads();

        const u32 bs = sb + (u32)(kc & 1) * 49152u;
        const u32 sAh = bs, sAl = bs + 16384u, sB = bs + 32768u;

#pragma unroll
        for (int ks = 0; ks < 4; ++ks) {
            u32 ah[4][4], al[4][4];
#pragma unroll
            for (int mi = 0; mi < 4; ++mi) {
                u32 ad = SWZ((u32)((wm + mi * 16 + (lane & 15)) * 128 +
                                   ks * 32 + (lane >> 4) * 16));
                ldmx4(ah[mi][0], ah[mi][1], ah[mi][2], ah[mi][3], sAh + ad);
                ldmx4(al[mi][0], al[mi][1], al[mi][2], al[mi][3], sAl + ad);
            }
            u32 bh[4][2];
#pragma unroll
            for (int nj = 0; nj < 2; ++nj) {
                u32 ad = SWZ((u32)((wn + nj * 16 + (lane & 15)) * 128 +
                                   ks * 32 + (lane >> 4) * 16));
                u32 r0, r1, r2, r3;
                ldmx4(r0, r1, r2, r3, sB + ad);
                bh[2 * nj][0] = r0; bh[2 * nj][1] = r2;
                bh[2 * nj + 1][0] = r1; bh[2 * nj + 1][1] = r3;
            }
#pragma unroll
            for (int mi = 0; mi < 4; ++mi)
#pragma unroll
                for (int nt = 0; nt < 4; ++nt) {
                    mma16816h(acc[mi][nt], ah[mi], bh[nt]);
                    mma16816h(acc[mi][nt], al[mi], bh[nt]);
                }
        }
        __syncthreads();
    }
}

// Fused QKV projections: grid (8, 64, 3); z selects operand set; fp16 out.
__global__ __launch_bounds__(256, 1) void gemm_qkv(QKVArgs args)
{
    extern __shared__ char sm[];
    const u32 sb = cvta_s(sm);
    const int tid = threadIdx.x, wid = tid >> 5, lane = tid & 31;
    const int n0 = blockIdx.x * 128, m0 = blockIdx.y * 128;
    const int wm = (wid >> 2) * 64, wn = (wid & 3) * 32;
    const int z = blockIdx.z;

    const half* Ah = args.Ah[z];
    const half* Al = args.Al[z];
    const half* Bh = args.Bh[z];
    const float* bias = args.bias[z];
    half* Out = args.Out[z];

    float acc[4][4][4];
    gemm2_mainloop(Ah, Al, Bh, sb, tid, m0, n0, wm, wn, lane, acc);

    const int g = lane >> 2, tq = lane & 3;
#pragma unroll
    for (int mi = 0; mi < 4; ++mi) {
        int row0 = m0 + wm + mi * 16 + g;
#pragma unroll
        for (int nt = 0; nt < 4; ++nt) {
            int col = n0 + wn + nt * 8 + tq * 2;
            float b0 = bias[col], b1 = bias[col + 1];
            *(u32*)(Out + (size_t)row0 * DMODEL + col) =
                pack2h(acc[mi][nt][0] + b0, acc[mi][nt][1] + b1);
            *(u32*)(Out + (size_t)(row0 + 8) * DMODEL + col) =
                pack2h(acc[mi][nt][2] + b0, acc[mi][nt][3] + b1);
        }
    }
}

// Final output GEMM: fp32 out.
__global__ __launch_bounds__(256, 1) void gemm_out(
    const half* __restrict__ Ah, const half* __restrict__ Al,
    const half* __restrict__ Bh, const float* __restrict__ bias,
    float* __restrict__ Cf)
{
    extern __shared__ char sm[];
    const u32 sb = cvta_s(sm);
    const int tid = threadIdx.x, wid = tid >> 5, lane = tid & 31;
    const int n0 = blockIdx.x * 128, m0 = blockIdx.y * 128;
    const int wm = (wid >> 2) * 64, wn = (wid & 3) * 32;

    float acc[4][4][4];
    gemm2_mainloop(Ah, Al, Bh, sb, tid, m0, n0, wm, wn, lane, acc);

    const int g = lane >> 2, tq = lane & 3;
#pragma unroll
    for (int mi = 0; mi < 4; ++mi) {
        int row0 = m0 + wm + mi * 16 + g;
#pragma unroll
        for (int nt = 0; nt < 4; ++nt) {
            int col = n0 + wn + nt * 8 + tq * 2;
            float b0 = bias[col], b1 = bias[col + 1];
            *(float2*)(Cf + (size_t)row0 * DMODEL + col) =
                make_float2(acc[mi][nt][0] + b0, acc[mi][nt][1] + b1);
            *(float2*)(Cf + (size_t)(row0 + 8) * DMODEL + col) =
                make_float2(acc[mi][nt][2] + b0, acc[mi][nt][3] + b1);
        }
    }
}

// ---------------------------------------------------------------------------
// fp16 HMMA flash attention:
//   S  = Q*K   (1 product; Q, K single fp16)
//   PV = P*V   (1 product; P single fp16 from regs, V single fp16)
// 128 q rows per CTA (8 warps x 16 rows), 64-row kv tiles, max-free softmax,
// O accumulated fp32 in registers, output split-fp16 (for the final GEMM).
// smem: Q 16K resident + 2 stages x [K 8K][V 8K] = 48 KB -> 2 CTAs/SM.
// ---------------------------------------------------------------------------
#define KV_ISSUE(st, t) do {                                                 \
    u32 bs_ = sb + 16384u + (u32)(st) * 16384u;                              \
    _Pragma("unroll")                                                        \
    for (int it_ = 0; it_ < 2; ++it_) {                                      \
        int i_ = tid + it_ * 256;                                            \
        int row_ = i_ >> 3, c_ = i_ & 7;                                     \
        u32 so_ = SWZ((u32)(row_ * 128 + c_ * 16));                          \
        size_t go_ = base + (size_t)((t) * 64 + row_) * DMODEL + c_ * 8;     \
        cpa16(bs_ + so_,         Kh_ + go_);                                 \
        cpa16(bs_ + 8192u + so_, Vh_ + go_);                                 \
    }                                                                        \
    cpcommit();                                                              \
} while (0)

__global__ __launch_bounds__(256, 2) void flash_h(
    const half* __restrict__ Qh_, const half* __restrict__ Kh_,
    const half* __restrict__ Vh_,
    half* __restrict__ Oh_, half* __restrict__ Ol_)
{
    extern __shared__ char sm[];
    const u32 sb = cvta_s(sm);
    const u32 sQ = sb;
    const int tid = threadIdx.x, wid = tid >> 5, lane = tid & 31;
    const int b = blockIdx.z, h = blockIdx.y, q0 = blockIdx.x * 128;
    const size_t base = ((size_t)b * SEQ) * DMODEL + (size_t)h * DK;

    // Load Q (128 x 64 fp16) and prefetch first K/V tile
#pragma unroll
    for (int it = 0; it < 4; ++it) {
        int i = tid + it * 256;
        int row = i >> 3, c = i & 7;
        u32 so = SWZ((u32)(row * 128 + c * 16));
        sts128(sQ + so, *(const uint4*)(Qh_ + base + (size_t)(q0 + row) * DMODEL + c * 8));
    }
    KV_ISSUE(0, 0);
    __syncthreads();

    // Preload Q fragments (Q smem stable for whole kernel)
    u32 qh[4][4];
#pragma unroll
    for (int ks = 0; ks < 4; ++ks) {
        u32 ad = SWZ((u32)((wid * 16 + (lane & 15)) * 128 +
                           ks * 32 + (lane >> 4) * 16));
        ldmx4(qh[ks][0], qh[ks][1], qh[ks][2], qh[ks][3], sQ + ad);
    }

    float oc[8][4];
#pragma unroll
    for (int nt = 0; nt < 8; ++nt)
#pragma unroll
        for (int e = 0; e < 4; ++e) oc[nt][e] = 0.f;
    float rs0 = 0.f, rs1 = 0.f;

    for (int t = 0; t < 32; ++t) {
        if (t < 31) KV_ISSUE((t + 1) & 1, t + 1);
        if (t < 31) cpwait1(); else cpwait0();
        __syncthreads();

        const u32 bs = sb + 16384u + (u32)(t & 1) * 16384u;
        const u32 sK = bs, sV = bs + 8192u;

        // ---- S = Q K^T ----
        float sc[8][4];
#pragma unroll
        for (int nt = 0; nt < 8; ++nt)
#pragma unroll
            for (int e = 0; e < 4; ++e) sc[nt][e] = 0.f;

#pragma unroll
        for (int ks = 0; ks < 4; ++ks) {
            u32 kh[8][2];
#pragma unroll
            for (int nj = 0; nj < 4; ++nj) {
                u32 ad = SWZ((u32)((nj * 16 + (lane & 15)) * 128 +
                                   ks * 32 + (lane >> 4) * 16));
                u32 r0, r1, r2, r3;
                ldmx4(r0, r1, r2, r3, sK + ad);
                kh[2 * nj][0] = r0; kh[2 * nj][1] = r2;
                kh[2 * nj + 1][0] = r1; kh[2 * nj + 1][1] = r3;
            }
#pragma unroll
            for (int nt = 0; nt < 8; ++nt)
                mma16816h(sc[nt], qh[ks], kh[nt]);
        }

        // ---- exp (max-free) + row-sum accumulation ----
#pragma unroll
        for (int nt = 0; nt < 8; ++nt) {
#pragma unroll
            for (int e = 0; e < 4; ++e) sc[nt][e] = __expf(sc[nt][e] * 0.125f);
            rs0 += sc[nt][0] + sc[nt][1];
            rs1 += sc[nt][2] + sc[nt][3];
        }

        // ---- O += P V  (P single fp16 from S frags; V via ldmatrix.trans) ----
#pragma unroll
        for (int ks = 0; ks < 4; ++ks) {
            const int j0 = 2 * ks, j1 = 2 * ks + 1;
            u32 ph[4];
            ph[0] = pack2h(sc[j0][0], sc[j0][1]);
            ph[1] = pack2h(sc[j0][2], sc[j0][3]);
            ph[2] = pack2h(sc[j1][0], sc[j1][1]);
            ph[3] = pack2h(sc[j1][2], sc[j1][3]);

            u32 vh[8][2];
#pragma unroll
            for (int dj = 0; dj < 4; ++dj) {
                u32 ad = SWZ((u32)((ks * 16 + (lane & 15)) * 128 +
                                   dj * 32 + (lane >> 4) * 16));
                u32 r0, r1, r2, r3;
                ldmx4t(r0, r1, r2, r3, sV + ad);
                vh[2 * dj][0] = r0; vh[2 * dj][1] = r1;
                vh[2 * dj + 1][0] = r2; vh[2 * dj + 1][1] = r3;
            }
#pragma unroll
            for (int nt = 0; nt < 8; ++nt)
                mma16816h(oc[nt], ph, vh[nt]);
        }
        __syncthreads();
    }

    // ---- epilogue: row-sum reduce, normalize, split-fp16 store ----
    rs0 += __shfl_xor_sync(0xffffffffu, rs0, 1);
    rs0 += __shfl_xor_sync(0xffffffffu, rs0, 2);
    rs1 += __shfl_xor_sync(0xffffffffu, rs1, 1);
    rs1 += __shfl_xor_sync(0xffffffffu, rs1, 2);
    const float inv0 = 1.f / rs0, inv1 = 1.f / rs1;

    const int g = lane >> 2, tq = lane & 3;
    const int row0 = q0 + wid * 16 + g;
#pragma unroll
    for (int nt = 0; nt < 8; ++nt) {
        int col = nt * 8 + tq * 2;
        u32 hp, lp;
        split_pack_h(oc[nt][0] * inv0, oc[nt][1] * inv0, hp, lp);
        *(u32*)(Oh_ + base + (size_t)row0 * DMODEL + col) = hp;
        *(u32*)(Ol_ + base + (size_t)row0 * DMODEL + col) = lp;
        split_pack_h(oc[nt][2] * inv1, oc[nt][3] * inv1, hp, lp);
        *(u32*)(Oh_ + base + (size_t)(row0 + 8) * DMODEL + col) = hp;
        *(u32*)(Ol_ + base + (size_t)(row0 + 8) * DMODEL + col) = lp;
    }
}

// ---------------------------------------------------------------------------
// Launch
// ---------------------------------------------------------------------------
extern "C" void kernel_launch(void* const* d_in, const int* in_sizes, int n_in,
                              void* d_out, int out_size)
{
    const float* query = (const float*)d_in[0];
    const float* key   = (const float*)d_in[1];
    const float* value = (const float*)d_in[2];
    const float* Wq = (const float*)d_in[3];
    const float* bq = (const float*)d_in[4];
    const float* Wk = (const float*)d_in[5];
    const float* bk = (const float*)d_in[6];
    const float* Wv = (const float*)d_in[7];
    const float* bv = (const float*)d_in[8];
    const float* Wo = (const float*)d_in[9];
    const float* bo = (const float*)d_in[10];
    float* out = (float*)d_out;

    half *act, *prjh, *obuf, *whbuf;
    cudaGetSymbolAddress((void**)&act,   g_act);
    cudaGetSymbolAddress((void**)&prjh,  g_prjh);
    cudaGetSymbolAddress((void**)&obuf,  g_o);
    cudaGetSymbolAddress((void**)&whbuf, g_wh);

    half *aq_h = act,          *aq_l = act + SZ;
    half *ak_h = act + 2 * SZ, *ak_l = act + 3 * SZ;
    half *av_h = act + 4 * SZ, *av_l = act + 5 * SZ;
    half *q_h = prjh, *k_h = prjh + SZ, *v_h = prjh + 2 * SZ;
    half *o_h = obuf, *o_l = obuf + SZ;
    half *wq_t = whbuf, *wk_t = whbuf + WSZ;
    half *wv_t = whbuf + 2 * WSZ, *wo_t = whbuf + 3 * WSZ;

    // Fused activation conversion (1 launch, grid.z = 3)
    const int n4 = (int)(SZ / 4);
    ConvActArgs ca;
    ca.x[0] = query; ca.x[1] = key; ca.x[2] = value;
    ca.h[0] = aq_h;  ca.h[1] = ak_h; ca.h[2] = av_h;
    ca.l[0] = aq_l;  ca.l[1] = ak_l; ca.l[2] = av_l;
    dim3 cag((n4 + 255) / 256, 1, 3);
    conv_act<<<cag, 256>>>(ca, n4);

    // Fused weight transpose+convert (1 launch, grid.z = 4)
    ConvWArgs cw;
    cw.W[0] = Wq; cw.W[1] = Wk; cw.W[2] = Wv; cw.W[3] = Wo;
    cw.T[0] = wq_t; cw.T[1] = wk_t; cw.T[2] = wv_t; cw.T[3] = wo_t;
    dim3 cwg(32, 32, 4), cwb(32, 8);
    conv_w<<<cwg, cwb>>>(cw);

    // Fused QKV projections (1 launch, grid.z = 3)
    const int g2sm = 98304;   // 2 stages x 48 KB (occupancy 1 — no reg cap)
    cudaFuncSetAttribute(gemm_qkv, cudaFuncAttributeMaxDynamicSharedMemorySize, g2sm);
    cudaFuncSetAttribute(gemm_out, cudaFuncAttributeMaxDynamicSharedMemorySize, g2sm);
    QKVArgs qa;
    qa.Ah[0] = aq_h; qa.Ah[1] = ak_h; qa.Ah[2] = av_h;
    qa.Al[0] = aq_l; qa.Al[1] = ak_l; qa.Al[2] = av_l;
    qa.Bh[0] = wq_t; qa.Bh[1] = wk_t; qa.Bh[2] = wv_t;
    qa.bias[0] = bq; qa.bias[1] = bk; qa.bias[2] = bv;
    qa.Out[0] = q_h; qa.Out[1] = k_h; qa.Out[2] = v_h;
    dim3 qg(DMODEL / 128, MROWS / 128, 3);   // (8, 64, 3)
    gemm_qkv<<<qg, 256, g2sm>>>(qa);

    // Flash attention
    const int fsm = 49152;    // Q 16 KB + 2 stages x 16 KB -> 2 CTAs/SM
    cudaFuncSetAttribute(flash_h, cudaFuncAttributeMaxDynamicSharedMemorySize, fsm);
    dim3 fgrid(SEQ / 128, NHEADS, BATCH);    // (16, 16, 4)
    flash_h<<<fgrid, 256, fsm>>>(q_h, k_h, v_h, o_h, o_l);

    // Final output GEMM: O (split-fp16) @ Wo (single fp16) -> fp32 out
    dim3 og(DMODEL / 128, MROWS / 128);      // (8, 64)
    gemm_out<<<og, 256, g2sm>>>(o_h, o_l, wo_t, bo, out);
}

// round 17
// speedup vs baseline: 1.1052x; 1.1052x over previous
#include <cuda_runtime.h>
#include <cuda_bf16.h>
#include <cuda_fp16.h>

#define DMODEL 1024
#define NHEADS 16
#define DK     64
#define BATCH  4
#define SEQ    2048
#define MROWS  (BATCH * SEQ)              // 8192
#define SZ     ((size_t)MROWS * DMODEL)   // 8388608 elems
#define WSZ    ((size_t)DMODEL * DMODEL)

typedef unsigned int u32;
typedef unsigned short u16;
typedef __nv_bfloat16 bf16;

// ---------------------------------------------------------------------------
// Device scratch (no allocation allowed)
// ---------------------------------------------------------------------------
__device__ half g_act[6 * SZ];    // [aq_h, aq_l, ak_h, ak_l, av_h, av_l] split-fp16
__device__ half g_prjh[3 * SZ];   // [q, k, v] single fp16
__device__ half g_o[2 * SZ];      // [o_h, o_l] split-fp16
__device__ half g_wh[4 * WSZ];    // [wqT, wkT, wvT, woT] single fp16 (transposed)

// ---------------------------------------------------------------------------
// PTX helpers (base-ISA only: ldmatrix + mma.sync + cp.async)
// ---------------------------------------------------------------------------
__device__ __forceinline__ u32 cvta_s(const void* p) {
    u32 a; asm("{ .reg .u64 t; cvta.to.shared.u64 t, %1; cvt.u32.u64 %0, t; }"
               : "=r"(a) : "l"(p)); return a;
}
__device__ __forceinline__ void sts128(u32 a, uint4 v) {
    asm volatile("st.shared.v4.b32 [%0], {%1,%2,%3,%4};"
                 :: "r"(a), "r"(v.x), "r"(v.y), "r"(v.z), "r"(v.w) : "memory");
}
__device__ __forceinline__ void cpa16(u32 s, const void* g) {
    asm volatile("{ .reg .u64 gg; cvta.to.global.u64 gg, %1;"
                 "  cp.async.cg.shared.global [%0], [gg], 16; }"
                 :: "r"(s), "l"(g) : "memory");
}
__device__ __forceinline__ void cpcommit() { asm volatile("cp.async.commit_group;" ::: "memory"); }
__device__ __forceinline__ void cpwait1()  { asm volatile("cp.async.wait_group 1;" ::: "memory"); }
__device__ __forceinline__ void cpwait0()  { asm volatile("cp.async.wait_group 0;" ::: "memory"); }

#define SWZ(x) ((x) ^ (((x) >> 3) & 0x70))

__device__ __forceinline__ void ldmx4(u32& r0, u32& r1, u32& r2, u32& r3, u32 a) {
    asm volatile("ldmatrix.sync.aligned.m8n8.x4.shared.b16 {%0,%1,%2,%3}, [%4];"
                 : "=r"(r0), "=r"(r1), "=r"(r2), "=r"(r3) : "r"(a));
}
__device__ __forceinline__ void ldmx4t(u32& r0, u32& r1, u32& r2, u32& r3, u32 a) {
    asm volatile("ldmatrix.sync.aligned.m8n8.x4.trans.shared.b16 {%0,%1,%2,%3}, [%4];"
                 : "=r"(r0), "=r"(r1), "=r"(r2), "=r"(r3) : "r"(a));
}
// fp16 MMA
__device__ __forceinline__ void mma16816h(float* d, const u32* a, const u32* b) {
    asm volatile(
        "mma.sync.aligned.m16n8k16.row.col.f32.f16.f16.f32 "
        "{%0,%1,%2,%3}, {%4,%5,%6,%7}, {%8,%9}, {%0,%1,%2,%3};"
        : "+f"(d[0]), "+f"(d[1]), "+f"(d[2]), "+f"(d[3])
        : "r"(a[0]), "r"(a[1]), "r"(a[2]), "r"(a[3]), "r"(b[0]), "r"(b[1]));
}
// fp16 helpers (x0 -> low half)
__device__ __forceinline__ u32 pack2h(float x0, float x1) {
    __half2 hh = __floats2half2_rn(x0, x1);
    return *reinterpret_cast<u32*>(&hh);
}
__device__ __forceinline__ void split_pack_h(float x0, float x1, u32& hp, u32& lp) {
    __half2 hh = __floats2half2_rn(x0, x1);
    hp = *reinterpret_cast<u32*>(&hh);
    float r0 = x0 - __low2float(hh);
    float r1 = x1 - __high2float(hh);
    __half2 ll = __floats2half2_rn(r0, r1);
    lp = *reinterpret_cast<u32*>(&ll);
}

// ---------------------------------------------------------------------------
// Pointer-bundle structs (passed by value to fused kernels)
// ---------------------------------------------------------------------------
struct ConvActArgs { const float* x[3]; half* h[3]; half* l[3]; };
struct ConvWArgs   { const float* W[4]; half* T[4]; };
struct QKVArgs {
    const half* Ah[3]; const half* Al[3]; const half* Bh[3];
    const float* bias[3]; half* Out[3];
};

// ---------------------------------------------------------------------------
// Fused conversion kernels
// ---------------------------------------------------------------------------
// fp32 -> split-fp16 (hi + lo); grid.z selects tensor
__global__ __launch_bounds__(256) void conv_act(ConvActArgs args, int n4)
{
    int i = blockIdx.x * 256 + threadIdx.x;
    if (i >= n4) return;
    const float* x = args.x[blockIdx.z];
    half* h = args.h[blockIdx.z];
    half* l = args.l[blockIdx.z];
    float4 v = ((const float4*)x)[i];
    float vv[4] = {v.x, v.y, v.z, v.w};
    u32 hp[2], lp[2];
#pragma unroll
    for (int e = 0; e < 2; ++e)
        split_pack_h(vv[2 * e], vv[2 * e + 1], hp[e], lp[e]);
    ((uint2*)h)[i] = make_uint2(hp[0], hp[1]);
    ((uint2*)l)[i] = make_uint2(lp[0], lp[1]);
}

// W[k][n] fp32 -> Wt[n][k] single fp16 (transpose through smem); grid.z selects
__global__ __launch_bounds__(256) void conv_w(ConvWArgs args)
{
    __shared__ float ts[32][33];
    const float* W = args.W[blockIdx.z];
    half* T = args.T[blockIdx.z];
    int tx = threadIdx.x, ty = threadIdx.y;         // 32 x 8
    int x0 = blockIdx.x * 32, y0 = blockIdx.y * 32; // x: n, y: k
#pragma unroll
    for (int i = 0; i < 4; ++i)
        ts[ty + i * 8][tx] = W[(size_t)(y0 + ty + i * 8) * DMODEL + x0 + tx];
    __syncthreads();
#pragma unroll
    for (int i = 0; i < 4; ++i) {
        int n = x0 + ty + i * 8, k = y0 + tx;
        T[(size_t)n * DMODEL + k] = __float2half_rn(ts[tx][ty + i * 8]);
    }
}

// ---------------------------------------------------------------------------
// 2-product split-A fp16 GEMM mainloop, re-tiled for 2 CTAs/SM:
// CTA tile 128M x 64N, K-chunk 64, 8 warps in a 4(M) x 2(N) grid,
// warp tile 32x32. acc = 32 regs -> total ~100 regs, fits the 128-reg cap
// of (256,2) WITHOUT spilling (unlike the round-12 128x128 variant).
// smem: 2 stages x [Ah 16K][Al 16K][B 8K] = 80 KB -> 2 CTAs/SM (160 KB).
// ---------------------------------------------------------------------------
#define G2_ISSUE(st, k0) do {                                                \
    u32 bs_ = sb + (u32)(st) * 40960u;                                       \
    _Pragma("unroll")                                                        \
    for (int it_ = 0; it_ < 4; ++it_) {                                      \
        int i_ = tid + it_ * 256;                                            \
        int row_ = i_ >> 3, c_ = i_ & 7;                                     \
        u32 so_ = SWZ((u32)(row_ * 128 + c_ * 16));                          \
        size_t ao_ = (size_t)(m0 + row_) * DMODEL + (k0) + c_ * 8;           \
        cpa16(bs_ + so_,          Ah + ao_);                                 \
        cpa16(bs_ + 16384u + so_, Al + ao_);                                 \
    }                                                                        \
    _Pragma("unroll")                                                        \
    for (int it_ = 0; it_ < 2; ++it_) {                                      \
        int i_ = tid + it_ * 256;                                            \
        int row_ = i_ >> 3, c_ = i_ & 7;                                     \
        u32 so_ = SWZ((u32)(row_ * 128 + c_ * 16));                          \
        size_t bo_ = (size_t)(n0 + row_) * DMODEL + (k0) + c_ * 8;           \
        cpa16(bs_ + 32768u + so_, Bh + bo_);                                 \
    }                                                                        \
    cpcommit();                                                              \
} while (0)

// Computes the 128x64 tile accumulator; caller handles the epilogue.
__device__ __forceinline__ void gemm2_mainloop(
    const half* __restrict__ Ah, const half* __restrict__ Al,
    const half* __restrict__ Bh,
    u32 sb, int tid, int m0, int n0, int wm, int wn, int lane,
    float acc[2][4][4])
{
#pragma unroll
    for (int mi = 0; mi < 2; ++mi)
#pragma unroll
        for (int nt = 0; nt < 4; ++nt)
#pragma unroll
            for (int e = 0; e < 4; ++e) acc[mi][nt][e] = 0.f;

    G2_ISSUE(0, 0);
    for (int kc = 0; kc < 16; ++kc) {
        if (kc < 15) G2_ISSUE((kc + 1) & 1, (kc + 1) * 64);
        if (kc < 15) cpwait1(); else cpwait0();
        __syncthreads();

        const u32 bs = sb + (u32)(kc & 1) * 40960u;
        const u32 sAh = bs, sAl = bs + 16384u, sB = bs + 32768u;

#pragma unroll
        for (int ks = 0; ks < 4; ++ks) {
            u32 ah[2][4], al[2][4];
#pragma unroll
            for (int mi = 0; mi < 2; ++mi) {
                u32 ad = SWZ((u32)((wm + mi * 16 + (lane & 15)) * 128 +
                                   ks * 32 + (lane >> 4) * 16));
                ldmx4(ah[mi][0], ah[mi][1], ah[mi][2], ah[mi][3], sAh + ad);
                ldmx4(al[mi][0], al[mi][1], al[mi][2], al[mi][3], sAl + ad);
            }
            u32 bh[4][2];
#pragma unroll
            for (int nj = 0; nj < 2; ++nj) {
                u32 ad = SWZ((u32)((wn + nj * 16 + (lane & 15)) * 128 +
                                   ks * 32 + (lane >> 4) * 16));
                u32 r0, r1, r2, r3;
                ldmx4(r0, r1, r2, r3, sB + ad);
                bh[2 * nj][0] = r0; bh[2 * nj][1] = r2;
                bh[2 * nj + 1][0] = r1; bh[2 * nj + 1][1] = r3;
            }
#pragma unroll
            for (int mi = 0; mi < 2; ++mi)
#pragma unroll
                for (int nt = 0; nt < 4; ++nt) {
                    mma16816h(acc[mi][nt], ah[mi], bh[nt]);
                    mma16816h(acc[mi][nt], al[mi], bh[nt]);
                }
        }
        __syncthreads();
    }
}

// Fused QKV projections: grid (16, 64, 3); z selects operand set; fp16 out.
__global__ __launch_bounds__(256, 2) void gemm_qkv(QKVArgs args)
{
    extern __shared__ char sm[];
    const u32 sb = cvta_s(sm);
    const int tid = threadIdx.x, wid = tid >> 5, lane = tid & 31;
    const int n0 = blockIdx.x * 64, m0 = blockIdx.y * 128;
    const int wm = (wid & 3) * 32, wn = (wid >> 2) * 32;
    const int z = blockIdx.z;

    const half* Ah = args.Ah[z];
    const half* Al = args.Al[z];
    const half* Bh = args.Bh[z];
    const float* bias = args.bias[z];
    half* Out = args.Out[z];

    float acc[2][4][4];
    gemm2_mainloop(Ah, Al, Bh, sb, tid, m0, n0, wm, wn, lane, acc);

    const int g = lane >> 2, tq = lane & 3;
#pragma unroll
    for (int mi = 0; mi < 2; ++mi) {
        int row0 = m0 + wm + mi * 16 + g;
#pragma unroll
        for (int nt = 0; nt < 4; ++nt) {
            int col = n0 + wn + nt * 8 + tq * 2;
            float b0 = bias[col], b1 = bias[col + 1];
            *(u32*)(Out + (size_t)row0 * DMODEL + col) =
                pack2h(acc[mi][nt][0] + b0, acc[mi][nt][1] + b1);
            *(u32*)(Out + (size_t)(row0 + 8) * DMODEL + col) =
                pack2h(acc[mi][nt][2] + b0, acc[mi][nt][3] + b1);
        }
    }
}

// Final output GEMM: fp32 out.
__global__ __launch_bounds__(256, 2) void gemm_out(
    const half* __restrict__ Ah, const half* __restrict__ Al,
    const half* __restrict__ Bh, const float* __restrict__ bias,
    float* __restrict__ Cf)
{
    extern __shared__ char sm[];
    const u32 sb = cvta_s(sm);
    const int tid = threadIdx.x, wid = tid >> 5, lane = tid & 31;
    const int n0 = blockIdx.x * 64, m0 = blockIdx.y * 128;
    const int wm = (wid & 3) * 32, wn = (wid >> 2) * 32;

    float acc[2][4][4];
    gemm2_mainloop(Ah, Al, Bh, sb, tid, m0, n0, wm, wn, lane, acc);

    const int g = lane >> 2, tq = lane & 3;
#pragma unroll
    for (int mi = 0; mi < 2; ++mi) {
        int row0 = m0 + wm + mi * 16 + g;
#pragma unroll
        for (int nt = 0; nt < 4; ++nt) {
            int col = n0 + wn + nt * 8 + tq * 2;
            float b0 = bias[col], b1 = bias[col + 1];
            *(float2*)(Cf + (size_t)row0 * DMODEL + col) =
                make_float2(acc[mi][nt][0] + b0, acc[mi][nt][1] + b1);
            *(float2*)(Cf + (size_t)(row0 + 8) * DMODEL + col) =
                make_float2(acc[mi][nt][2] + b0, acc[mi][nt][3] + b1);
        }
    }
}

// ---------------------------------------------------------------------------
// fp16 HMMA flash attention (unchanged from round 14/15):
//   S  = Q*K   (1 product; Q, K single fp16)
//   PV = P*V   (1 product; P single fp16 from regs, V single fp16)
// 128 q rows per CTA (8 warps x 16 rows), 64-row kv tiles, max-free softmax,
// O accumulated fp32 in registers, output split-fp16 (for the final GEMM).
// smem: Q 16K resident + 2 stages x [K 8K][V 8K] = 48 KB -> 2 CTAs/SM.
// ---------------------------------------------------------------------------
#define KV_ISSUE(st, t) do {                                                 \
    u32 bs_ = sb + 16384u + (u32)(st) * 16384u;                              \
    _Pragma("unroll")                                                        \
    for (int it_ = 0; it_ < 2; ++it_) {                                      \
        int i_ = tid + it_ * 256;                                            \
        int row_ = i_ >> 3, c_ = i_ & 7;                                     \
        u32 so_ = SWZ((u32)(row_ * 128 + c_ * 16));                          \
        size_t go_ = base + (size_t)((t) * 64 + row_) * DMODEL + c_ * 8;     \
        cpa16(bs_ + so_,         Kh_ + go_);                                 \
        cpa16(bs_ + 8192u + so_, Vh_ + go_);                                 \
    }                                                                        \
    cpcommit();                                                              \
} while (0)

__global__ __launch_bounds__(256, 2) void flash_h(
    const half* __restrict__ Qh_, const half* __restrict__ Kh_,
    const half* __restrict__ Vh_,
    half* __restrict__ Oh_, half* __restrict__ Ol_)
{
    extern __shared__ char sm[];
    const u32 sb = cvta_s(sm);
    const u32 sQ = sb;
    const int tid = threadIdx.x, wid = tid >> 5, lane = tid & 31;
    const int b = blockIdx.z, h = blockIdx.y, q0 = blockIdx.x * 128;
    const size_t base = ((size_t)b * SEQ) * DMODEL + (size_t)h * DK;

    // Load Q (128 x 64 fp16) and prefetch first K/V tile
#pragma unroll
    for (int it = 0; it < 4; ++it) {
        int i = tid + it * 256;
        int row = i >> 3, c = i & 7;
        u32 so = SWZ((u32)(row * 128 + c * 16));
        sts128(sQ + so, *(const uint4*)(Qh_ + base + (size_t)(q0 + row) * DMODEL + c * 8));
    }
    KV_ISSUE(0, 0);
    __syncthreads();

    // Preload Q fragments (Q smem stable for whole kernel)
    u32 qh[4][4];
#pragma unroll
    for (int ks = 0; ks < 4; ++ks) {
        u32 ad = SWZ((u32)((wid * 16 + (lane & 15)) * 128 +
                           ks * 32 + (lane >> 4) * 16));
        ldmx4(qh[ks][0], qh[ks][1], qh[ks][2], qh[ks][3], sQ + ad);
    }

    float oc[8][4];
#pragma unroll
    for (int nt = 0; nt < 8; ++nt)
#pragma unroll
        for (int e = 0; e < 4; ++e) oc[nt][e] = 0.f;
    float rs0 = 0.f, rs1 = 0.f;

    for (int t = 0; t < 32; ++t) {
        if (t < 31) KV_ISSUE((t + 1) & 1, t + 1);
        if (t < 31) cpwait1(); else cpwait0();
        __syncthreads();

        const u32 bs = sb + 16384u + (u32)(t & 1) * 16384u;
        const u32 sK = bs, sV = bs + 8192u;

        // ---- S = Q K^T ----
        float sc[8][4];
#pragma unroll
        for (int nt = 0; nt < 8; ++nt)
#pragma unroll
            for (int e = 0; e < 4; ++e) sc[nt][e] = 0.f;

#pragma unroll
        for (int ks = 0; ks < 4; ++ks) {
            u32 kh[8][2];
#pragma unroll
            for (int nj = 0; nj < 4; ++nj) {
                u32 ad = SWZ((u32)((nj * 16 + (lane & 15)) * 128 +
                                   ks * 32 + (lane >> 4) * 16));
                u32 r0, r1, r2, r3;
                ldmx4(r0, r1, r2, r3, sK + ad);
                kh[2 * nj][0] = r0; kh[2 * nj][1] = r2;
                kh[2 * nj + 1][0] = r1; kh[2 * nj + 1][1] = r3;
            }
#pragma unroll
            for (int nt = 0; nt < 8; ++nt)
                mma16816h(sc[nt], qh[ks], kh[nt]);
        }

        // ---- exp (max-free) + row-sum accumulation ----
#pragma unroll
        for (int nt = 0; nt < 8; ++nt) {
#pragma unroll
            for (int e = 0; e < 4; ++e) sc[nt][e] = __expf(sc[nt][e] * 0.125f);
            rs0 += sc[nt][0] + sc[nt][1];
            rs1 += sc[nt][2] + sc[nt][3];
        }

        // ---- O += P V  (P single fp16 from S frags; V via ldmatrix.trans) ----
#pragma unroll
        for (int ks = 0; ks < 4; ++ks) {
            const int j0 = 2 * ks, j1 = 2 * ks + 1;
            u32 ph[4];
            ph[0] = pack2h(sc[j0][0], sc[j0][1]);
            ph[1] = pack2h(sc[j0][2], sc[j0][3]);
            ph[2] = pack2h(sc[j1][0], sc[j1][1]);
            ph[3] = pack2h(sc[j1][2], sc[j1][3]);

            u32 vh[8][2];
#pragma unroll
            for (int dj = 0; dj < 4; ++dj) {
                u32 ad = SWZ((u32)((ks * 16 + (lane & 15)) * 128 +
                                   dj * 32 + (lane >> 4) * 16));
                u32 r0, r1, r2, r3;
                ldmx4t(r0, r1, r2, r3, sV + ad);
                vh[2 * dj][0] = r0; vh[2 * dj][1] = r1;
                vh[2 * dj + 1][0] = r2; vh[2 * dj + 1][1] = r3;
            }
#pragma unroll
            for (int nt = 0; nt < 8; ++nt)
                mma16816h(oc[nt], ph, vh[nt]);
        }
        __syncthreads();
    }

    // ---- epilogue: row-sum reduce, normalize, split-fp16 store ----
    rs0 += __shfl_xor_sync(0xffffffffu, rs0, 1);
    rs0 += __shfl_xor_sync(0xffffffffu, rs0, 2);
    rs1 += __shfl_xor_sync(0xffffffffu, rs1, 1);
    rs1 += __shfl_xor_sync(0xffffffffu, rs1, 2);
    const float inv0 = 1.f / rs0, inv1 = 1.f / rs1;

    const int g = lane >> 2, tq = lane & 3;
    const int row0 = q0 + wid * 16 + g;
#pragma unroll
    for (int nt = 0; nt < 8; ++nt) {
        int col = nt * 8 + tq * 2;
        u32 hp, lp;
        split_pack_h(oc[nt][0] * inv0, oc[nt][1] * inv0, hp, lp);
        *(u32*)(Oh_ + base + (size_t)row0 * DMODEL + col) = hp;
        *(u32*)(Ol_ + base + (size_t)row0 * DMODEL + col) = lp;
        split_pack_h(oc[nt][2] * inv1, oc[nt][3] * inv1, hp, lp);
        *(u32*)(Oh_ + base + (size_t)(row0 + 8) * DMODEL + col) = hp;
        *(u32*)(Ol_ + base + (size_t)(row0 + 8) * DMODEL + col) = lp;
    }
}

// ---------------------------------------------------------------------------
// Launch
// ---------------------------------------------------------------------------
extern "C" void kernel_launch(void* const* d_in, const int* in_sizes, int n_in,
                              void* d_out, int out_size)
{
    const float* query = (const float*)d_in[0];
    const float* key   = (const float*)d_in[1];
    const float* value = (const float*)d_in[2];
    const float* Wq = (const float*)d_in[3];
    const float* bq = (const float*)d_in[4];
    const float* Wk = (const float*)d_in[5];
    const float* bk = (const float*)d_in[6];
    const float* Wv = (const float*)d_in[7];
    const float* bv = (const float*)d_in[8];
    const float* Wo = (const float*)d_in[9];
    const float* bo = (const float*)d_in[10];
    float* out = (float*)d_out;

    half *act, *prjh, *obuf, *whbuf;
    cudaGetSymbolAddress((void**)&act,   g_act);
    cudaGetSymbolAddress((void**)&prjh,  g_prjh);
    cudaGetSymbolAddress((void**)&obuf,  g_o);
    cudaGetSymbolAddress((void**)&whbuf, g_wh);

    half *aq_h = act,          *aq_l = act + SZ;
    half *ak_h = act + 2 * SZ, *ak_l = act + 3 * SZ;
    half *av_h = act + 4 * SZ, *av_l = act + 5 * SZ;
    half *q_h = prjh, *k_h = prjh + SZ, *v_h = prjh + 2 * SZ;
    half *o_h = obuf, *o_l = obuf + SZ;
    half *wq_t = whbuf, *wk_t = whbuf + WSZ;
    half *wv_t = whbuf + 2 * WSZ, *wo_t = whbuf + 3 * WSZ;

    // Fused activation conversion (1 launch, grid.z = 3)
    const int n4 = (int)(SZ / 4);
    ConvActArgs ca;
    ca.x[0] = query; ca.x[1] = key; ca.x[2] = value;
    ca.h[0] = aq_h;  ca.h[1] = ak_h; ca.h[2] = av_h;
    ca.l[0] = aq_l;  ca.l[1] = ak_l; ca.l[2] = av_l;
    dim3 cag((n4 + 255) / 256, 1, 3);
    conv_act<<<cag, 256>>>(ca, n4);

    // Fused weight transpose+convert (1 launch, grid.z = 4)
    ConvWArgs cw;
    cw.W[0] = Wq; cw.W[1] = Wk; cw.W[2] = Wv; cw.W[3] = Wo;
    cw.T[0] = wq_t; cw.T[1] = wk_t; cw.T[2] = wv_t; cw.T[3] = wo_t;
    dim3 cwg(32, 32, 4), cwb(32, 8);
    conv_w<<<cwg, cwb>>>(cw);

    // Fused QKV projections (1 launch, grid.z = 3), 2 CTAs/SM tiles
    const int g2sm = 81920;   // 2 stages x 40 KB -> 2 CTAs/SM (160 KB)
    cudaFuncSetAttribute(gemm_qkv, cudaFuncAttributeMaxDynamicSharedMemorySize, g2sm);
    cudaFuncSetAttribute(gemm_out, cudaFuncAttributeMaxDynamicSharedMemorySize, g2sm);
    QKVArgs qa;
    qa.Ah[0] = aq_h; qa.Ah[1] = ak_h; qa.Ah[2] = av_h;
    qa.Al[0] = aq_l; qa.Al[1] = ak_l; qa.Al[2] = av_l;
    qa.Bh[0] = wq_t; qa.Bh[1] = wk_t; qa.Bh[2] = wv_t;
    qa.bias[0] = bq; qa.bias[1] = bk; qa.bias[2] = bv;
    qa.Out[0] = q_h; qa.Out[1] = k_h; qa.Out[2] = v_h;
    dim3 qg(DMODEL / 64, MROWS / 128, 3);    // (16, 64, 3)
    gemm_qkv<<<qg, 256, g2sm>>>(qa);

    // Flash attention
    const int fsm = 49152;    // Q 16 KB + 2 stages x 16 KB -> 2 CTAs/SM
    cudaFuncSetAttribute(flash_h, cudaFuncAttributeMaxDynamicSharedMemorySize, fsm);
    dim3 fgrid(SEQ / 128, NHEADS, BATCH);    // (16, 16, 4)
    flash_h<<<fgrid, 256, fsm>>>(q_h, k_h, v_h, o_h, o_l);

    // Final output GEMM: O (split-fp16) @ Wo (single fp16) -> fp32 out
    dim3 og(DMODEL / 64, MROWS / 128);       // (16, 64)
    gemm_out<<<og, 256, g2sm>>>(o_h, o_l, wo_t, bo, out);
}